// round 6
// baseline (speedup 1.0000x reference)
#include <cuda_runtime.h>
#include <cuda_bf16.h>
#include <math.h>
#include <stdint.h>

#define SQ    2048
#define HIDD  2048
#define NH    16
#define NOPE  128
#define ROPE  64
#define VDIM  128
#define QD    192   // NOPE + ROPE
#define QLR   1536
#define KVLR  512
#define KVDN  576   // KVLR + ROPE

// GEMM tiling
#define BM    128
#define BN    128
#define BK    16
#define TPB   512
#define LDT   24                       // bf16 row stride (48B): conflict-friendly ldmatrix
#define TILE_E  (BM * LDT)             // 3072 bf16 per plane
#define STAGE_E (4 * TILE_E)           // planes: Ah, Al, Bh, Bl
#define STAGES  4
#define SMEM_BYTES (STAGES * STAGE_E * 2)   // 96 KB

// ---------------- fp32 scratch ----------------
__device__ __align__(256) float g_qc [SQ * QLR];
__device__ __align__(256) float g_kvd[SQ * KVDN];
__device__ __align__(256) float g_q  [SQ * NH * QD];
__device__ __align__(256) float g_kv [SQ * NH * (NOPE + VDIM)];
__device__ __align__(256) float g_ctx[SQ * NH * VDIM];
__device__ __align__(256) float g_cos[SQ * 32];
__device__ __align__(256) float g_sin[SQ * 32];

// ---------------- bf16 hi/lo planes ----------------
__device__ __align__(256) __nv_bfloat16 p_hs_h [SQ * HIDD],      p_hs_l [SQ * HIDD];
__device__ __align__(256) __nv_bfloat16 p_wqd_h[QLR * HIDD],     p_wqd_l[QLR * HIDD];
__device__ __align__(256) __nv_bfloat16 p_wkd_h[KVDN * HIDD],    p_wkd_l[KVDN * HIDD];
__device__ __align__(256) __nv_bfloat16 p_wqu_h[NH*QD * QLR],    p_wqu_l[NH*QD * QLR];
__device__ __align__(256) __nv_bfloat16 p_wku_h[NH*256 * KVLR],  p_wku_l[NH*256 * KVLR];
__device__ __align__(256) __nv_bfloat16 p_wo_h [HIDD * NH*VDIM], p_wo_l [HIDD * NH*VDIM];
__device__ __align__(256) __nv_bfloat16 p_qcn_h[SQ * QLR],       p_qcn_l[SQ * QLR];
__device__ __align__(256) __nv_bfloat16 p_ckv_h[SQ * KVLR],      p_ckv_l[SQ * KVLR];
__device__ __align__(256) __nv_bfloat16 p_qal_h[(long long)NH*SQ*QD], p_qal_l[(long long)NH*SQ*QD];
__device__ __align__(256) __nv_bfloat16 p_kal_h[(long long)NH*SQ*QD], p_kal_l[(long long)NH*SQ*QD];
__device__ __align__(256) __nv_bfloat16 p_vt_h [(long long)NH*VDIM*SQ], p_vt_l [(long long)NH*VDIM*SQ];
__device__ __align__(256) __nv_bfloat16 p_at_h [(long long)NH*SQ*SQ],   p_at_l [(long long)NH*SQ*SQ];
__device__ __align__(256) __nv_bfloat16 p_ctx_h[SQ * NH*VDIM],   p_ctx_l[SQ * NH*VDIM];

// ---------------- primitives ----------------
__device__ __forceinline__ void ldsm4(uint32_t* r, uint32_t addr) {
    asm volatile("ldmatrix.sync.aligned.m8n8.x4.shared.b16 {%0,%1,%2,%3}, [%4];"
        : "=r"(r[0]), "=r"(r[1]), "=r"(r[2]), "=r"(r[3]) : "r"(addr));
}
__device__ __forceinline__ void mma_bf16(float* d, const uint32_t* a,
                                         uint32_t b0, uint32_t b1) {
    asm volatile(
        "mma.sync.aligned.m16n8k16.row.col.f32.bf16.bf16.f32 "
        "{%0,%1,%2,%3}, {%4,%5,%6,%7}, {%8,%9}, {%0,%1,%2,%3};"
        : "+f"(d[0]), "+f"(d[1]), "+f"(d[2]), "+f"(d[3])
        : "r"(a[0]), "r"(a[1]), "r"(a[2]), "r"(a[3]), "r"(b0), "r"(b1));
}
__device__ __forceinline__ void cpasync16(uint32_t dst, const void* src, int srcbytes) {
    asm volatile("cp.async.cg.shared.global [%0], [%1], 16, %2;"
        :: "r"(dst), "l"(src), "r"(srcbytes));
}
#define CP_COMMIT()   asm volatile("cp.async.commit_group;")
#define CP_WAIT2()    asm volatile("cp.async.wait_group 2;")

__device__ __forceinline__ void split1(float v, __nv_bfloat16& h, __nv_bfloat16& l) {
    h = __float2bfloat16(v);
    l = __float2bfloat16(v - __bfloat162float(h));
}
__device__ __forceinline__ void split4v(float4 v, uint2& hi, uint2& lo) {
    __nv_bfloat16 h0, h1, h2, h3, l0, l1, l2, l3;
    split1(v.x, h0, l0); split1(v.y, h1, l1);
    split1(v.z, h2, l2); split1(v.w, h3, l3);
    __nv_bfloat162 p;
    p = __halves2bfloat162(h0, h1); hi.x = *reinterpret_cast<uint32_t*>(&p);
    p = __halves2bfloat162(h2, h3); hi.y = *reinterpret_cast<uint32_t*>(&p);
    p = __halves2bfloat162(l0, l1); lo.x = *reinterpret_cast<uint32_t*>(&p);
    p = __halves2bfloat162(l2, l3); lo.y = *reinterpret_cast<uint32_t*>(&p);
}

// ---------------------------------------------------------------------------
// Planar bf16 tensor-core GEMM: C[M,N] = alpha * (A @ B^T) + bias
// A, B given as bf16 hi/lo planes; product = Ah*Bh + Ah*Bl + Al*Bh.
// CTA tile 128x128, 16 warps (32x32 each), k-chunk 16, 4-stage cp.async pipe.
// Requires M%128==0, K%16==0, lda/ldb%8==0 (true at all call sites). N guarded.
// causal=1: skip blocks above diagonal. causal=2: Kend = m0+128.
// ---------------------------------------------------------------------------
__global__ __launch_bounds__(TPB, 1) void gemm_planar(
    const __nv_bfloat16* __restrict__ Ah, const __nv_bfloat16* __restrict__ Al,
    const __nv_bfloat16* __restrict__ Bh, const __nv_bfloat16* __restrict__ Bl,
    float* __restrict__ C, const float* __restrict__ bias,
    int M, int N, int K, int lda, int ldb, int ldc,
    long long sA, long long sB, long long sC,
    float alpha, int causal)
{
    extern __shared__ __nv_bfloat16 sm[];

    const int z = blockIdx.z;
    Ah += (long long)z * sA;  Al += (long long)z * sA;
    Bh += (long long)z * sB;  Bl += (long long)z * sB;
    C  += (long long)z * sC;

    const int m0 = blockIdx.y * BM;
    const int n0 = blockIdx.x * BN;
    if (causal == 1 && n0 > m0 + BM - 1) return;
    const int Kend = (causal == 2) ? min(K, m0 + BM) : K;
    const int nchunks = Kend / BK;

    const int tid  = threadIdx.x;
    const int wid  = tid >> 5;
    const int lane = tid & 31;
    const int wm   = (wid & 3) * 32;
    const int wn   = (wid >> 2) * 32;

    // ---- cp.async loader mapping: tid<256 -> A planes, else B planes ----
    const int  lrow  = (tid & 255) >> 1;     // 0..127
    const int  lhalf = (tid & 1) * 8;        // elem 0 or 8
    const bool isA   = tid < 256;
    long long grow = m0 + lrow;
    int vbytes = 16;
    int gld = lda;
    const __nv_bfloat16 *gH = Ah, *gL = Al;
    if (!isA) {
        gld = ldb; gH = Bh; gL = Bl;
        if (n0 + lrow < N) grow = n0 + lrow; else { grow = 0; vbytes = 0; }
    }
    const __nv_bfloat16* srcH = gH + grow * gld + lhalf;
    const __nv_bfloat16* srcL = gL + grow * gld + lhalf;
    const int planeBase = (isA ? 0 : 2) * TILE_E + lrow * LDT + lhalf;

    const uint32_t smbase = (uint32_t)__cvta_generic_to_shared(sm);

    // ldmatrix per-lane offsets
    const int aoff = (wm + (lane & 15)) * LDT + (lane >> 4) * 8;
    const int boff = (wn + (lane & 15)) * LDT + (lane >> 4) * 8;

    float acc[2][4][4];
    #pragma unroll
    for (int i = 0; i < 2; i++)
        #pragma unroll
        for (int j = 0; j < 4; j++)
            #pragma unroll
            for (int l = 0; l < 4; l++) acc[i][j][l] = 0.f;

    // ---- prologue: fill STAGES-1 stages ----
    #pragma unroll
    for (int c = 0; c < STAGES - 1; c++) {
        if (c < nchunks) {
            const uint32_t d = smbase + 2u * ((c % STAGES) * STAGE_E + planeBase);
            cpasync16(d,                  srcH + c * BK, vbytes);
            cpasync16(d + 2u * TILE_E,    srcL + c * BK, vbytes);
        }
        CP_COMMIT();
    }

    for (int ic = 0; ic < nchunks; ic++) {
        CP_WAIT2();
        __syncthreads();

        // issue chunk ic+3 into the stage freed last iteration
        const int nc = ic + STAGES - 1;
        if (nc < nchunks) {
            const uint32_t d = smbase + 2u * ((nc % STAGES) * STAGE_E + planeBase);
            cpasync16(d,               srcH + nc * BK, vbytes);
            cpasync16(d + 2u * TILE_E, srcL + nc * BK, vbytes);
        }
        CP_COMMIT();

        // ---- compute on stage ic%STAGES ----
        const uint32_t sb = smbase + 2u * ((ic % STAGES) * STAGE_E);
        uint32_t af[2][4], bh[2][4], bl[2][4];
        ldsm4(af[0], sb + 2u * (0 * TILE_E + aoff));
        ldsm4(af[1], sb + 2u * (0 * TILE_E + aoff + 16 * LDT));
        ldsm4(bh[0], sb + 2u * (2 * TILE_E + boff));
        ldsm4(bh[1], sb + 2u * (2 * TILE_E + boff + 16 * LDT));
        ldsm4(bl[0], sb + 2u * (3 * TILE_E + boff));
        ldsm4(bl[1], sb + 2u * (3 * TILE_E + boff + 16 * LDT));

        #pragma unroll
        for (int mb = 0; mb < 2; mb++)
            #pragma unroll
            for (int nb = 0; nb < 4; nb++) {
                const int gI = nb >> 1, hI = nb & 1;
                mma_bf16(acc[mb][nb], af[mb], bh[gI][hI], bh[gI][2 + hI]);  // hi*hi
                mma_bf16(acc[mb][nb], af[mb], bl[gI][hI], bl[gI][2 + hI]);  // hi*lo
            }

        ldsm4(af[0], sb + 2u * (1 * TILE_E + aoff));
        ldsm4(af[1], sb + 2u * (1 * TILE_E + aoff + 16 * LDT));
        #pragma unroll
        for (int mb = 0; mb < 2; mb++)
            #pragma unroll
            for (int nb = 0; nb < 4; nb++) {
                const int gI = nb >> 1, hI = nb & 1;
                mma_bf16(acc[mb][nb], af[mb], bh[gI][hI], bh[gI][2 + hI]);  // lo*hi
            }
        __syncthreads();
    }

    // ---- epilogue ----
    const bool hasBias = (bias != nullptr);
    const int gI = lane >> 2;
    const int t2 = (lane & 3) * 2;
    #pragma unroll
    for (int mb = 0; mb < 2; mb++) {
        #pragma unroll
        for (int nb = 0; nb < 4; nb++) {
            const int r = m0 + wm + mb * 16 + gI;
            const int c = n0 + wn + nb * 8 + t2;
            float* Cr0 = C + (long long)r * ldc;
            float* Cr1 = C + (long long)(r + 8) * ldc;
            if (c < N) {
                float b0 = hasBias ? bias[c] : 0.f;
                Cr0[c] = alpha * acc[mb][nb][0] + b0;
                Cr1[c] = alpha * acc[mb][nb][2] + b0;
            }
            if (c + 1 < N) {
                float b1 = hasBias ? bias[c + 1] : 0.f;
                Cr0[c + 1] = alpha * acc[mb][nb][1] + b1;
                Cr1[c + 1] = alpha * acc[mb][nb][3] + b1;
            }
        }
    }
}

// ---------------------------------------------------------------------------
// fp32 -> planar hi/lo split (vectorized by 4)
// ---------------------------------------------------------------------------
__global__ void split_f32(const float* __restrict__ x,
                          __nv_bfloat16* __restrict__ h, __nv_bfloat16* __restrict__ l,
                          int n4)
{
    const int i = blockIdx.x * blockDim.x + threadIdx.x;
    if (i < n4) {
        float4 v = reinterpret_cast<const float4*>(x)[i];
        uint2 hi, lo;
        split4v(v, hi, lo);
        reinterpret_cast<uint2*>(h)[i] = hi;
        reinterpret_cast<uint2*>(l)[i] = lo;
    }
}

// ---------------------------------------------------------------------------
// RMSNorm over rows, writing hi/lo planes: o = g * x * rsqrt(mean(x^2)+eps)
// ---------------------------------------------------------------------------
__global__ void rmsnorm_split(const float* __restrict__ x,
                              __nv_bfloat16* __restrict__ oh, __nv_bfloat16* __restrict__ ol,
                              const float* __restrict__ g, int width, int in_ld, int out_ld)
{
    const int r = blockIdx.x;
    const float* row = x + (long long)r * in_ld;
    __shared__ float red[256];
    float s = 0.f;
    for (int i = threadIdx.x; i < width; i += 256) {
        float v = row[i];
        s += v * v;
    }
    red[threadIdx.x] = s;
    __syncthreads();
    for (int st = 128; st > 0; st >>= 1) {
        if (threadIdx.x < st) red[threadIdx.x] += red[threadIdx.x + st];
        __syncthreads();
    }
    const float inv = rsqrtf(red[0] / (float)width + 1e-6f);
    for (int i = threadIdx.x; i < width; i += 256) {
        const float v = g[i] * (row[i] * inv);
        __nv_bfloat16 h, l;
        split1(v, h, l);
        oh[(long long)r * out_ld + i] = h;
        ol[(long long)r * out_ld + i] = l;
    }
}

// ---------------------------------------------------------------------------
// RoPE table (double trig on f32-rounded angle, matches reference rounding)
// ---------------------------------------------------------------------------
__global__ void rope_table(const int* __restrict__ pos)
{
    const int s = blockIdx.x;
    const int j = threadIdx.x;          // 0..31
    const double invf = pow(10000.0, -(double)j / 32.0);
    const float  ang  = (float)pos[s] * (float)invf;
    g_cos[s * 32 + j] = (float)cos((double)ang);
    g_sin[s * 32 + j] = (float)sin((double)ang);
}

// ---------------------------------------------------------------------------
// Build head-major q_all / k_all (RoPE applied), writing hi/lo planes.
// ---------------------------------------------------------------------------
__global__ void assemble_rope(const float* __restrict__ q, const float* __restrict__ kv,
                              const float* __restrict__ kvd)
{
    const int s = blockIdx.x;

    for (int e = threadIdx.x; e < NH * QD; e += blockDim.x) {
        const int h = e / QD, d = e % QD;
        float qa, ka;
        if (d < NOPE) {
            qa = q [(long long)s * (NH * QD) + h * QD + d];
            ka = kv[(long long)s * (NH * 256) + h * 256 + d];
        } else {
            const int j  = d - NOPE;
            const int jj = (j < 32) ? j : j - 32;
            const float c  = g_cos[s * 32 + jj];
            const float sn = g_sin[s * 32 + jj];
            const long long qb = (long long)s * (NH * QD) + h * QD + NOPE;
            const float qx = q[qb + 2 * jj];
            const float qy = q[qb + 2 * jj + 1];
            const long long kb = (long long)s * KVDN + KVLR;
            const float kx = kvd[kb + 2 * jj];
            const float ky = kvd[kb + 2 * jj + 1];
            if (j < 32) { qa = qx * c - qy * sn; ka = kx * c - ky * sn; }
            else        { qa = qy * c + qx * sn; ka = ky * c + kx * sn; }
        }
        const long long o = ((long long)h * SQ + s) * QD + d;
        __nv_bfloat16 hh, ll;
        split1(qa, hh, ll); p_qal_h[o] = hh; p_qal_l[o] = ll;
        split1(ka, hh, ll); p_kal_h[o] = hh; p_kal_l[o] = ll;
    }
}

// ---------------------------------------------------------------------------
// V transpose to [h][d][s], writing hi/lo planes.
// ---------------------------------------------------------------------------
__global__ void transpose_v(const float* __restrict__ kv)
{
    __shared__ float t[32][33];
    const int h  = blockIdx.z;
    const int S0 = blockIdx.x * 32;
    const int D0 = blockIdx.y * 32;
    const int tx = threadIdx.x, ty = threadIdx.y;   // 32 x 8

    #pragma unroll
    for (int j = 0; j < 4; j++) {
        const int s = S0 + ty + j * 8;
        t[ty + j * 8][tx] = kv[(long long)s * (NH * 256) + h * 256 + NOPE + D0 + tx];
    }
    __syncthreads();
    #pragma unroll
    for (int j = 0; j < 4; j++) {
        const int d = D0 + ty + j * 8;
        const float v = t[tx][ty + j * 8];
        const long long o = ((long long)h * VDIM + d) * SQ + S0 + tx;
        __nv_bfloat16 hh, ll;
        split1(v, hh, ll);
        p_vt_h[o] = hh; p_vt_l[o] = ll;
    }
}

// ---------------------------------------------------------------------------
// Causal softmax in place (fp32 out) + hi/lo plane output; zero-fills k > q.
// ---------------------------------------------------------------------------
__global__ void softmax_causal(float* __restrict__ attn)
{
    const long long row = blockIdx.x;
    const int q = (int)(row % SQ);
    float* p = attn + row * SQ;
    __nv_bfloat16* ph = p_at_h + row * SQ;
    __nv_bfloat16* pl = p_at_l + row * SQ;
    const int valid = q + 1;

    __shared__ float red[256];
    const int t = threadIdx.x;

    float vals[8];
    float mx = -INFINITY;
    #pragma unroll
    for (int i = 0; i < 8; i++) {
        const int k = t + i * 256;
        vals[i] = (k < valid) ? p[k] : -INFINITY;
        mx = fmaxf(mx, vals[i]);
    }
    red[t] = mx;
    __syncthreads();
    for (int st = 128; st > 0; st >>= 1) {
        if (t < st) red[t] = fmaxf(red[t], red[t + st]);
        __syncthreads();
    }
    mx = red[0];
    __syncthreads();

    float sm = 0.f;
    #pragma unroll
    for (int i = 0; i < 8; i++) {
        const float e = (vals[i] == -INFINITY) ? 0.f : expf(vals[i] - mx);
        vals[i] = e;
        sm += e;
    }
    red[t] = sm;
    __syncthreads();
    for (int st = 128; st > 0; st >>= 1) {
        if (t < st) red[t] += red[t + st];
        __syncthreads();
    }
    const float inv = 1.f / red[0];
    #pragma unroll
    for (int i = 0; i < 8; i++) {
        const int k = t + i * 256;
        const float v = vals[i] * inv;
        p[k] = v;
        __nv_bfloat16 hh, ll;
        split1(v, hh, ll);
        ph[k] = hh; pl[k] = ll;
    }
}

// ---------------------------------------------------------------------------
extern "C" void kernel_launch(void* const* d_in, const int* in_sizes, int n_in,
                              void* d_out, int out_size)
{
    const float* hs       = (const float*)d_in[0];
    const int*   pos      = (const int*)  d_in[1];
    // d_in[2] = causal_mask — causality derived from indices instead
    const float* Wq_down  = (const float*)d_in[3];
    const float* bq_down  = (const float*)d_in[4];
    const float* gq_norm  = (const float*)d_in[5];
    const float* Wq_up    = (const float*)d_in[6];
    const float* Wkv_down = (const float*)d_in[7];
    const float* bkv_down = (const float*)d_in[8];
    const float* gkv_norm = (const float*)d_in[9];
    const float* Wkv_up   = (const float*)d_in[10];
    const float* Wo       = (const float*)d_in[11];

    float* out  = (float*)d_out;                       // [S, HID]
    float* attn = out + (long long)SQ * HIDD;          // [H, S, S]

    static bool attrSet = false;
    if (!attrSet) {
        cudaFuncSetAttribute(gemm_planar, cudaFuncAttributeMaxDynamicSharedMemorySize,
                             SMEM_BYTES);
        attrSet = true;
    }

    float *qc, *kvd, *q, *kv, *ctx;
    cudaGetSymbolAddress((void**)&qc,  g_qc);
    cudaGetSymbolAddress((void**)&kvd, g_kvd);
    cudaGetSymbolAddress((void**)&q,   g_q);
    cudaGetSymbolAddress((void**)&kv,  g_kv);
    cudaGetSymbolAddress((void**)&ctx, g_ctx);

    __nv_bfloat16 *hsh,*hsl,*wqdh,*wqdl,*wkdh,*wkdl,*wquh,*wqul,*wkuh,*wkul,*woh,*wol;
    __nv_bfloat16 *qcnh,*qcnl,*ckvh,*ckvl,*qalh,*qall_,*kalh,*kall_,*vth,*vtl,*ath,*atl,*ctxh,*ctxl;
    cudaGetSymbolAddress((void**)&hsh,  p_hs_h);  cudaGetSymbolAddress((void**)&hsl,  p_hs_l);
    cudaGetSymbolAddress((void**)&wqdh, p_wqd_h); cudaGetSymbolAddress((void**)&wqdl, p_wqd_l);
    cudaGetSymbolAddress((void**)&wkdh, p_wkd_h); cudaGetSymbolAddress((void**)&wkdl, p_wkd_l);
    cudaGetSymbolAddress((void**)&wquh, p_wqu_h); cudaGetSymbolAddress((void**)&wqul, p_wqu_l);
    cudaGetSymbolAddress((void**)&wkuh, p_wku_h); cudaGetSymbolAddress((void**)&wkul, p_wku_l);
    cudaGetSymbolAddress((void**)&woh,  p_wo_h);  cudaGetSymbolAddress((void**)&wol,  p_wo_l);
    cudaGetSymbolAddress((void**)&qcnh, p_qcn_h); cudaGetSymbolAddress((void**)&qcnl, p_qcn_l);
    cudaGetSymbolAddress((void**)&ckvh, p_ckv_h); cudaGetSymbolAddress((void**)&ckvl, p_ckv_l);
    cudaGetSymbolAddress((void**)&qalh, p_qal_h); cudaGetSymbolAddress((void**)&qall_,p_qal_l);
    cudaGetSymbolAddress((void**)&kalh, p_kal_h); cudaGetSymbolAddress((void**)&kall_,p_kal_l);
    cudaGetSymbolAddress((void**)&vth,  p_vt_h);  cudaGetSymbolAddress((void**)&vtl,  p_vt_l);
    cudaGetSymbolAddress((void**)&ath,  p_at_h);  cudaGetSymbolAddress((void**)&atl,  p_at_l);
    cudaGetSymbolAddress((void**)&ctxh, p_ctx_h); cudaGetSymbolAddress((void**)&ctxl, p_ctx_l);

    const dim3 blk(TPB);
    #define SPLIT(src, dh, dl, n) \
        split_f32<<<((n)/4 + 255)/256, 256>>>(src, dh, dl, (n)/4)

    // 0) RoPE table + operand splits
    rope_table<<<SQ, 32>>>(pos);
    SPLIT(hs,       hsh,  hsl,  SQ * HIDD);
    SPLIT(Wq_down,  wqdh, wqdl, QLR * HIDD);
    SPLIT(Wkv_down, wkdh, wkdl, KVDN * HIDD);
    SPLIT(Wq_up,    wquh, wqul, NH * QD * QLR);
    SPLIT(Wkv_up,   wkuh, wkul, NH * 256 * KVLR);
    SPLIT(Wo,       woh,  wol,  HIDD * NH * VDIM);

    // 1) qc = hs @ Wq_down^T + bq_down              [2048, 1536]
    gemm_planar<<<dim3(QLR / BN, SQ / BM, 1), blk, SMEM_BYTES>>>(
        hsh, hsl, wqdh, wqdl, qc, bq_down, SQ, QLR, HIDD, HIDD, HIDD, QLR,
        0, 0, 0, 1.f, 0);

    // 2) kvd = hs @ Wkv_down^T + bkv_down           [2048, 576]
    gemm_planar<<<dim3((KVDN + BN - 1) / BN, SQ / BM, 1), blk, SMEM_BYTES>>>(
        hsh, hsl, wkdh, wkdl, kvd, bkv_down, SQ, KVDN, HIDD, HIDD, HIDD, KVDN,
        0, 0, 0, 1.f, 0);

    // 3) rmsnorm -> planes
    rmsnorm_split<<<SQ, 256>>>(qc,  qcnh, qcnl, gq_norm,  QLR,  QLR,  QLR);
    rmsnorm_split<<<SQ, 256>>>(kvd, ckvh, ckvl, gkv_norm, KVLR, KVDN, KVLR);

    // 4) q = qcn @ Wq_up^T                          [2048, 3072]
    gemm_planar<<<dim3(NH * QD / BN, SQ / BM, 1), blk, SMEM_BYTES>>>(
        qcnh, qcnl, wquh, wqul, q, nullptr, SQ, NH * QD, QLR, QLR, QLR, NH * QD,
        0, 0, 0, 1.f, 0);

    // 5) kv = ckv @ Wkv_up^T                        [2048, 4096]
    gemm_planar<<<dim3(NH * 256 / BN, SQ / BM, 1), blk, SMEM_BYTES>>>(
        ckvh, ckvl, wkuh, wkul, kv, nullptr, SQ, NH * 256, KVLR, KVLR, KVLR, NH * 256,
        0, 0, 0, 1.f, 0);

    // 6) assemble q_all/k_all planes (RoPE); transpose V planes
    assemble_rope<<<SQ, 256>>>(q, kv, kvd);
    transpose_v<<<dim3(SQ / 32, VDIM / 32, NH), dim3(32, 8)>>>(kv);

    // 7) scores = (q_all @ k_all^T)/sqrt(QD), per head, causal-block-skip
    const float scale = 1.f / sqrtf((float)QD);
    gemm_planar<<<dim3(SQ / BN, SQ / BM, NH), blk, SMEM_BYTES>>>(
        qalh, qall_, kalh, kall_, attn, nullptr, SQ, SQ, QD, QD, QD, SQ,
        (long long)SQ * QD, (long long)SQ * QD, (long long)SQ * SQ,
        scale, 1);

    // 8) causal softmax in place + attn planes
    softmax_causal<<<NH * SQ, 256>>>(attn);

    // 9) ctx = attn @ vT^T, per head, K truncated at diagonal
    gemm_planar<<<dim3(1, SQ / BM, NH), blk, SMEM_BYTES>>>(
        ath, atl, vth, vtl, ctx, nullptr, SQ, VDIM, SQ, SQ, SQ, NH * VDIM,
        (long long)SQ * SQ, (long long)VDIM * SQ, (long long)VDIM,
        1.f, 2);

    // 9b) split ctx
    SPLIT(ctx, ctxh, ctxl, SQ * NH * VDIM);

    // 10) out = ctx @ Wo^T                          [2048, 2048]
    gemm_planar<<<dim3(HIDD / BN, SQ / BM, 1), blk, SMEM_BYTES>>>(
        ctxh, ctxl, woh, wol, out, nullptr, SQ, HIDD, NH * VDIM, NH * VDIM, NH * VDIM, HIDD,
        0, 0, 0, 1.f, 0);
}